// round 14
// baseline (speedup 1.0000x reference)
#include <cuda_runtime.h>
#include <cuda_fp16.h>
#include <cstdint>

// out[100000,128] = x[100000,128] @ (Wc+Wn)[128,128] + b[128]
// (gamma/segment-sum in the reference is dead code; edge_index unused)
//
// fp16 mma.sync (m16n8k16), f32 accum. CTA 128x128, 8 warps of 32x64.
// Warp PAIRS {2p,2p+1} share a 32-row x slice. KC=64: only 2 chunks/tile,
// all cp.async issued up-front (W | x0 | x1), 2 barriers total per tile.
//
// Inputs: d_in[0]=x f32 [100000,128], d_in[1]=edge_index i64 (UNUSED),
//         d_in[2]=Wc f32 [128,128], d_in[3]=Wn f32 [128,128], d_in[4]=b f32 [128]

#define D 128
#define TILE_M 128
#define KC 64
#define S72 72                    // x row stride (f32): 36 mod 16 = 4 -> conflict-free LDS.64
#define XWS (32 * S72)            // 2304 floats per pair-stage (32 rows x 64 k)
#define WC32 2048                 // W words per K=32 sub-chunk (128n x 32k fp16)

// W fp16x2 fragment image, 8192 words:
//   w = ((((c*2+wn)*2+s)*8 + j)*32 + lane)*2 + breg     (c = K/32 sub-chunk)
//   n = wn*64 + j*8 + (lane>>2), k0 = c*32 + s*16 + breg*8 + 2*(lane&3)
__device__ uint32_t g_Wh[8192];

__global__ void prep_w_kernel(const float* __restrict__ Wc,
                              const float* __restrict__ Wn) {
    int w = blockIdx.x * blockDim.x + threadIdx.x;
    if (w >= 8192) return;
    int breg = w & 1, lane = (w >> 1) & 31, j = (w >> 6) & 7;
    int s = (w >> 9) & 1, wn = (w >> 10) & 1, c = w >> 11;
    int n = wn * 64 + j * 8 + (lane >> 2);
    int k0 = c * 32 + s * 16 + breg * 8 + 2 * (lane & 3);
    float v0 = Wc[k0 * D + n] + Wn[k0 * D + n];
    float v1 = Wc[(k0 + 1) * D + n] + Wn[(k0 + 1) * D + n];
    __half2 h = __floats2half2_rn(v0, v1);
    g_Wh[w] = *reinterpret_cast<uint32_t*>(&h);
}

#define MMA_F16(c, a0, a1, a2, a3, b0, b1)                                    \
    asm volatile(                                                             \
        "mma.sync.aligned.m16n8k16.row.col.f32.f16.f16.f32 "                  \
        "{%0,%1,%2,%3}, {%4,%5,%6,%7}, {%8,%9}, {%0,%1,%2,%3};"               \
        : "+f"((c)[0]), "+f"((c)[1]), "+f"((c)[2]), "+f"((c)[3])              \
        : "r"(a0), "r"(a1), "r"(a2), "r"(a3), "r"(b0), "r"(b1))

__device__ __forceinline__ void cp_async16(uint32_t dst, const void* src, int valid) {
    asm volatile("cp.async.cg.shared.global [%0], [%1], 16, %2;"
                 :: "r"(dst), "l"(src), "r"(valid ? 16 : 0));
}

__device__ __forceinline__ uint32_t packh2(float lo, float hi) {
    __half2 h = __floats2half2_rn(lo, hi);
    return *reinterpret_cast<uint32_t*>(&h);
}

__global__ __launch_bounds__(256, 2)
void gemm_f16_kernel(const float* __restrict__ x,
                     const float* __restrict__ bias,
                     float* __restrict__ out, int nrows) {
    extern __shared__ float sm[];
    float* xs = sm;                                   // [4 pairs][2 stages][2304]
    uint32_t* ws = (uint32_t*)(sm + 8 * XWS);         // [8192] fp16x2 W frags

    const int tid = threadIdx.x;
    const int lane = tid & 31;
    const int wid = tid >> 5;
    const int g = lane >> 2;
    const int t4 = lane & 3;
    const int wm = wid >> 1;          // 0..3 = pair id (32 rows each)
    const int wn = wid & 1;           // 0..1 (64 cols)
    const int row0 = blockIdx.x * TILE_M;
    const int prow0 = row0 + wm * 32; // pair's first row

    const int ptid = tid & 63;        // thread within pair
    const int plr = ptid >> 3;        // 0..7 (row base)
    const int plj = ptid & 7;         // float4 col 0..7

    const uint32_t xs_b = (uint32_t)__cvta_generic_to_shared(xs) +
                          (uint32_t)(wm * 2 * XWS) * 4;
    const uint32_t ws_b = (uint32_t)__cvta_generic_to_shared(ws);

    // pair-local x slice: 32 rows x 64 k = 512 float4, 64 threads, 8 each
    auto load_x_chunk = [&](int k0, int stage) {
        uint32_t xd = xs_b + (uint32_t)(stage * XWS) * 4;
#pragma unroll
        for (int kit = 0; kit < 2; kit++) {
#pragma unroll
            for (int it = 0; it < 4; it++) {
                int r = plr + 8 * it;             // 0..31
                int grow = prow0 + r;
                int kcol = (plj + 8 * kit) * 4;   // 0..60
                cp_async16(xd + (uint32_t)(r * S72 + kcol) * 4,
                           x + (size_t)grow * D + k0 + kcol, grow < nrows);
            }
        }
        asm volatile("cp.async.commit_group;" ::: "memory");
    };

    // ---- prologue: W (group 0) | x chunk0 (group 1) | x chunk1 (group 2) ----
#pragma unroll
    for (int it = 0; it < 8; it++) {              // 2048 float4s of W (32KB)
        int idx = tid + 256 * it;
        cp_async16(ws_b + (uint32_t)idx * 16, g_Wh + ((size_t)idx << 2), 1);
    }
    asm volatile("cp.async.commit_group;" ::: "memory");
    load_x_chunk(0, 0);
    load_x_chunk(KC, 1);

    float acc[2][8][4];
#pragma unroll
    for (int i = 0; i < 2; i++)
#pragma unroll
        for (int j = 0; j < 8; j++)
#pragma unroll
            for (int p = 0; p < 4; p++) acc[i][j][p] = 0.0f;

    const uint32_t* wb_base = ws + wn * 1024 + lane * 2;
    const int barid = wm + 1;

#pragma unroll
    for (int C = 0; C < 2; C++) {
        if (C == 0) {
            asm volatile("cp.async.wait_group 1;" ::: "memory");  // W + x0
            __syncthreads();
        } else {
            asm volatile("cp.async.wait_group 0;" ::: "memory");  // x1
            asm volatile("bar.sync %0, 64;" :: "r"(barid) : "memory");
        }

        const float* xb = xs + (wm * 2 + C) * XWS;

#pragma unroll
        for (int kk = 0; kk < 2; kk++) {          // K=32 sub-chunks
            const int c32 = C * 2 + kk;           // W sub-chunk index
            const uint32_t* wc = wb_base + c32 * WC32;
#pragma unroll
            for (int s = 0; s < 2; s++) {
                uint32_t b[8][2];
#pragma unroll
                for (int j = 0; j < 8; j++) {
                    uint2 v = *(const uint2*)(wc + s * 512 + j * 64);
                    b[j][0] = v.x;
                    b[j][1] = v.y;
                }
#pragma unroll
                for (int i = 0; i < 2; i++) {
                    const float* xr = xb + (i * 16 + g) * S72 +
                                      kk * 32 + s * 16 + 2 * t4;
                    float2 v0 = *(const float2*)(xr);               // row g
                    float2 v1 = *(const float2*)(xr + 8 * S72);     // row g+8
                    float2 v2 = *(const float2*)(xr + 8);           // k +8
                    float2 v3 = *(const float2*)(xr + 8 * S72 + 8);
                    uint32_t a0 = packh2(v0.x, v0.y);
                    uint32_t a1 = packh2(v1.x, v1.y);
                    uint32_t a2 = packh2(v2.x, v2.y);
                    uint32_t a3 = packh2(v3.x, v3.y);
#pragma unroll
                    for (int j = 0; j < 8; j++)
                        MMA_F16(acc[i][j], a0, a1, a2, a3, b[j][0], b[j][1]);
                }
            }
        }
    }

    // ---- epilogue: bias + store directly from accumulators ----
#pragma unroll
    for (int j = 0; j < 8; j++) {
        int col = wn * 64 + 8 * j + 2 * t4;
        float b0 = __ldg(bias + col), b1 = __ldg(bias + col + 1);
#pragma unroll
        for (int i = 0; i < 2; i++) {
            int r_lo = prow0 + 16 * i + g;
            int r_hi = r_lo + 8;
            if (r_lo < nrows) {
                float2 v = make_float2(acc[i][j][0] + b0, acc[i][j][1] + b1);
                *(float2*)(out + (size_t)r_lo * D + col) = v;
            }
            if (r_hi < nrows) {
                float2 v = make_float2(acc[i][j][2] + b0, acc[i][j][3] + b1);
                *(float2*)(out + (size_t)r_hi * D + col) = v;
            }
        }
    }
}

extern "C" void kernel_launch(void* const* d_in, const int* in_sizes, int n_in,
                              void* d_out, int out_size) {
    const float* x    = (const float*)d_in[0];
    const float* Wc   = (const float*)d_in[2];
    const float* Wn   = (const float*)d_in[3];
    const float* bias = (const float*)d_in[4];
    float* out = (float*)d_out;

    const int nrows = in_sizes[0] / D;                 // 100000

    prep_w_kernel<<<32, 256>>>(Wc, Wn);

    const int smem_bytes = 8 * XWS * 4 + 8192 * 4;     // 73,728 + 32,768 = 106,496 B
    cudaFuncSetAttribute(gemm_f16_kernel,
                         cudaFuncAttributeMaxDynamicSharedMemorySize, smem_bytes);

    int grid = (nrows + TILE_M - 1) / TILE_M;          // 782
    gemm_f16_kernel<<<grid, 256, smem_bytes>>>(x, bias, out, nrows);
}